// round 14
// baseline (speedup 1.0000x reference)
#include <cuda_runtime.h>
#include <cuda_fp16.h>
#include <cstdint>

#define NN    50000
#define EE    400000
#define NREL  8
#define NLAY  5
#define WPB   8            // warps per block (gather)
#define NCOL  1536         // GEMM N: 1024 G | 256 Xr | 64 B | 64 roots | pad
#define SROW  772          // smem row stride in half2 (bank-conflict-free)

typedef unsigned int u32;

// ---------------- scratch (static device globals; no allocations) ----------
__device__ __half   g_WcatH[NLAY][NCOL * 32];    // fused fp16 weights, col-major [j][i]
__device__ __half2  g_roots[NN * 32];            // per-node (rroot,nroot) pairs
__device__ float    g_h[2][NN * 32];
__device__ float    g_invrel[NREL][NN];
__device__ int      g_counter[2];
__device__ int      g_outdeg[NN];
__device__ int      g_indeg[NN];
__device__ int      g_cursor[NN];
__device__ int      g_incur[NN];
__device__ int      g_rowptr[NN];
__device__ int      g_inrow[NN];
__device__ int4     g_erec[EE];                  // {r, wr_bits, dist_bits, dst_slot}
__device__ u32      g_msg2[2][(size_t)EE * 32];  // double-buffered per-edge msgs

__device__ __forceinline__ u32 pack_h2(float a, float b) {
    __half2 h = __floats2half2_rn(a, b);
    return *(u32*)&h;
}

// ---------------- init / counts ----------------------------------------------
__global__ void init_kernel() {
    int i = blockIdx.x * blockDim.x + threadIdx.x;
    if (i < 2) g_counter[i] = 0;
    if (i < NN) { g_outdeg[i] = 0; g_indeg[i] = 0; }
    if (i < NN * NREL) ((float*)g_invrel)[i] = 0.f;
}

__global__ void count_kernel(const int* __restrict__ src,
                             const int* __restrict__ dst,
                             const int* __restrict__ etype) {
    int e = blockIdx.x * blockDim.x + threadIdx.x;
    if (e >= EE) return;
    int d = dst[e], r = etype[e];
    atomicAdd(&g_indeg[d], 1);
    atomicAdd(&g_invrel[r][d], 1.f);
    atomicAdd(&g_outdeg[src[e]], 1);
}

// invert rel counts + assign CSR segments (order-free)
__global__ void assign_kernel() {
    int i = blockIdx.x * blockDim.x + threadIdx.x;
    if (i < NN * NREL) {
        float v = ((float*)g_invrel)[i];
        ((float*)g_invrel)[i] = 1.f / fmaxf(v, 1.f);
    }
    if (i < NN) {
        g_rowptr[i] = atomicAdd(&g_counter[0], g_outdeg[i]);
        g_inrow[i]  = atomicAdd(&g_counter[1], g_indeg[i]);
        g_cursor[i] = 0;
        g_incur[i]  = 0;
    }
}

__global__ void fill_kernel(const int* __restrict__ src,
                            const int* __restrict__ dst,
                            const int* __restrict__ etype,
                            const float* __restrict__ edist) {
    int e = blockIdx.x * blockDim.x + threadIdx.x;
    if (e >= EE) return;
    int s = src[e], d = dst[e], r = etype[e];
    int pos = g_rowptr[s] + atomicAdd(&g_cursor[s], 1);
    int pin = g_inrow[d] + atomicAdd(&g_incur[d], 1);
    int4 rec;
    rec.x = r;
    rec.y = __float_as_int(g_invrel[r][d]);
    rec.z = __float_as_int(edist[e]);
    rec.w = pin;
    g_erec[pos] = rec;
}

// ---------------- build fused fp16 weight matrix, col-major [j][i] -----------
__global__ void wcat_kernel(const float* __restrict__ W2,
                            const float* __restrict__ rW,
                            const float* __restrict__ b2,
                            const float* __restrict__ rroot,
                            const float* __restrict__ nroot) {
    int idx = blockIdx.x * blockDim.x + threadIdx.x;
    if (idx >= NLAY * NCOL * 32) return;
    int l = idx / (NCOL * 32);
    int rem = idx % (NCOL * 32);
    int j = rem >> 5, i = rem & 31;
    int p = j >> 1, par = j & 1;
    float v = 0.f;
    if (p < 512) {
        int k = 2 * (p >> 5) + par, o = p & 31;
        v = W2[k * 1024 + i * 32 + o];
    } else if (p < 640) {
        int r = 2 * ((p - 512) >> 5) + par, o = p & 31;
        v = rW[(((size_t)l * NREL + r) * 32 + i) * 32 + o];
    } else if (p < 672) {
        if (par == 0) v = b2[i * 32 + (p - 640)];
    } else if (p < 704) {
        int o = p - 672;
        v = par ? nroot[((size_t)l * 32 + i) * 32 + o]
                : rroot[((size_t)l * 32 + i) * 32 + o];
    }
    g_WcatH[l][rem] = __float2half(v);
}

// ---------------- h0 = relu(x @ fc_W + fc_b) --------------------------------
__global__ __launch_bounds__(WPB * 32) void fc_kernel(
    const float* __restrict__ x, const float* __restrict__ W,
    const float* __restrict__ b) {
    int warp = threadIdx.x >> 5, lane = threadIdx.x & 31;
    int n = blockIdx.x * WPB + warp;
    if (n >= NN) return;
    float xv = x[n * 32 + lane];
    float acc = b[lane];
#pragma unroll
    for (int k = 0; k < 32; k++)
        acc = fmaf(__shfl_sync(0xffffffffu, xv, k), W[k * 32 + lane], acc);
    g_h[0][n * 32 + lane] = fmaxf(acc, 0.f);
}

// ---------------- in-kernel gather/combine for one node ----------------------
__device__ __forceinline__ float gather_node(int n, int lane, int p, int mb,
                                             const float* rbias,
                                             const float* nbias) {
    int beg = g_inrow[n], cnt = g_indeg[n];
    const u32* base = &g_msg2[mb][(size_t)beg * 32 + lane];
    float mms = 0.f, dvs = 0.f;
    int j = 0;
    for (; j + 8 <= cnt; j += 8) {
        u32 v0 = base[(j + 0) * 32];
        u32 v1 = base[(j + 1) * 32];
        u32 v2 = base[(j + 2) * 32];
        u32 v3 = base[(j + 3) * 32];
        u32 v4 = base[(j + 4) * 32];
        u32 v5 = base[(j + 5) * 32];
        u32 v6 = base[(j + 6) * 32];
        u32 v7 = base[(j + 7) * 32];
        float2 f0 = __half22float2(*(__half2*)&v0);
        float2 f1 = __half22float2(*(__half2*)&v1);
        float2 f2 = __half22float2(*(__half2*)&v2);
        float2 f3 = __half22float2(*(__half2*)&v3);
        float2 f4 = __half22float2(*(__half2*)&v4);
        float2 f5 = __half22float2(*(__half2*)&v5);
        float2 f6 = __half22float2(*(__half2*)&v6);
        float2 f7 = __half22float2(*(__half2*)&v7);
        mms += ((f0.x + f1.x) + (f2.x + f3.x)) + ((f4.x + f5.x) + (f6.x + f7.x));
        dvs += ((f0.y + f1.y) + (f2.y + f3.y)) + ((f4.y + f5.y) + (f6.y + f7.y));
    }
    for (; j < cnt; j++) {
        u32 v = base[j * 32];
        float2 f = __half22float2(*(__half2*)&v);
        mms += f.x;
        dvs += f.y;
    }
    float invd = 1.f / fmaxf((float)cnt, 1.f);
    size_t idx = (size_t)n * 32 + lane;
    float2 roots = __half22float2(g_roots[idx]);
    float hv = g_h[p][idx];
    return hv + fmaxf(roots.x + rbias[lane] + dvs, 0.f)
              + fmaxf(roots.y + nbias[lane] + mms * invd, 0.f);
}

// ---------------- fused gather + GEMM(mma) + message kernel ------------------
// 512 threads, 32 nodes/block.
// Phase 0 (l>0): finish layer l-1 for this block's nodes (gather msg buffer
//                (l-1)&1 + combine) and write h_l (block-local consumption).
// Phase 1: 16 warps each own 32 distinct cols per pass (3 passes), both m-tiles.
// Phase 2: dynamic node queue; msgs written to buffer l&1 (no cross-layer race).
__global__ __launch_bounds__(512, 2) void fusedmsg_kernel(
    int p, int l, const float* __restrict__ W1, const float* __restrict__ b1,
    const float* __restrict__ prb, const float* __restrict__ pnb,
    int do_gather) {
    extern __shared__ __half2 sG[];        // [32][SROW], 96.5 KB
    __shared__ float sW1d[32];             // W1[0][k]
    __shared__ float sW1rb[NREL][32];      // W1[1+r][k] + b1[k]
    __shared__ int   sNext;
    int t = threadIdx.x, warp = t >> 5, lane = t & 31;
    int nblk = blockIdx.x * 32;
    int g = lane >> 2, tq = lane & 3;
    const __half* Wl = g_WcatH[l];
    int mbw = l & 1;           // msg buffer this layer writes
    int mbr = (l - 1) & 1;     // msg buffer phase 0 reads

    if (t == 0) sNext = 0;
    if (t < 32) sW1d[t] = W1[t];
    else if (t >= 64 && t < 320) {
        int r = (t - 64) >> 5, k = t & 31;
        sW1rb[r][k] = W1[(1 + r) * 32 + k] + b1[k];
    }

    int ph = p;   // buffer the GEMM reads
    if (do_gather) {
        // phase 0: 16 warps x 2 nodes — finish previous layer for our nodes
#pragma unroll
        for (int nn = 0; nn < 2; nn++) {
            int n = nblk + warp * 2 + nn;
            if (n < NN)
                g_h[p ^ 1][(size_t)n * 32 + lane] =
                    gather_node(n, lane, p, mbr, prb, pnb);
        }
        ph = p ^ 1;
        __syncthreads();   // make g_h[ph] visible block-wide
    }
    const float* hp = g_h[ph];

    // ---- load A fragments for both m-tiles ----
    u32 afrag[2][2][4];
#pragma unroll
    for (int m = 0; m < 2; m++) {
        int nodeA = nblk + m * 16 + g;
        int nodeB = nodeA + 8;
        bool vA = nodeA < NN, vB = nodeB < NN;
#pragma unroll
        for (int kk = 0; kk < 2; kk++) {
            int kb = kk * 16 + tq * 2;
            float2 f00 = vA ? *(const float2*)&hp[(size_t)nodeA * 32 + kb]
                            : make_float2(0.f, 0.f);
            float2 f01 = vA ? *(const float2*)&hp[(size_t)nodeA * 32 + kb + 8]
                            : make_float2(0.f, 0.f);
            float2 f10 = vB ? *(const float2*)&hp[(size_t)nodeB * 32 + kb]
                            : make_float2(0.f, 0.f);
            float2 f11 = vB ? *(const float2*)&hp[(size_t)nodeB * 32 + kb + 8]
                            : make_float2(0.f, 0.f);
            afrag[m][kk][0] = pack_h2(f00.x, f00.y);
            afrag[m][kk][1] = pack_h2(f10.x, f10.y);
            afrag[m][kk][2] = pack_h2(f01.x, f01.y);
            afrag[m][kk][3] = pack_h2(f11.x, f11.y);
        }
    }

    // ---- phase 1: 3 passes of 512 cols; warp covers 32 distinct cols ----
#pragma unroll
    for (int by2 = 0; by2 < 3; by2++) {
        float acc[2][4][4];
#pragma unroll
        for (int m = 0; m < 2; m++)
#pragma unroll
            for (int nt = 0; nt < 4; nt++)
#pragma unroll
                for (int c = 0; c < 4; c++) acc[m][nt][c] = 0.f;
#pragma unroll
        for (int kk = 0; kk < 2; kk++) {
#pragma unroll
            for (int nt = 0; nt < 4; nt++) {
                int j = by2 * 512 + warp * 32 + nt * 8 + g;
                u32 b0 = *(const u32*)&Wl[j * 32 + kk * 16 + tq * 2];
                u32 b1v = *(const u32*)&Wl[j * 32 + kk * 16 + tq * 2 + 8];
#pragma unroll
                for (int m = 0; m < 2; m++) {
                    asm("mma.sync.aligned.m16n8k16.row.col.f32.f16.f16.f32 "
                        "{%0,%1,%2,%3}, {%4,%5,%6,%7}, {%8,%9}, {%0,%1,%2,%3};"
                        : "+f"(acc[m][nt][0]), "+f"(acc[m][nt][1]),
                          "+f"(acc[m][nt][2]), "+f"(acc[m][nt][3])
                        : "r"(afrag[m][kk][0]), "r"(afrag[m][kk][1]),
                          "r"(afrag[m][kk][2]), "r"(afrag[m][kk][3]),
                          "r"(b0), "r"(b1v));
                }
            }
        }
#pragma unroll
        for (int m = 0; m < 2; m++)
#pragma unroll
            for (int nt = 0; nt < 4; nt++) {
                int pl = by2 * 256 + warp * 16 + nt * 4 + tq;
                sG[(m * 16 + g) * SROW + pl] =
                    __floats2half2_rn(acc[m][nt][0], acc[m][nt][1]);
                sG[(m * 16 + 8 + g) * SROW + pl] =
                    __floats2half2_rn(acc[m][nt][2], acc[m][nt][3]);
            }
    }
    __syncthreads();

    // ---- export roots (pairs 672..703) ----
#pragma unroll
    for (int it = 0; it < 2; it++) {
        int id = it * 512 + t;
        int node = id >> 5, o = id & 31;
        if (nblk + node < NN)
            g_roots[(size_t)(nblk + node) * 32 + o] = sG[node * SROW + 672 + o];
    }

    // ---- phase 2: dynamic node queue ----
    u32* msgw = g_msg2[mbw];
    int edge = lane >> 4, kk2 = (lane & 15) * 2;
    while (true) {
        int node = 0;
        if (lane == 0) node = atomicAdd(&sNext, 1);
        node = __shfl_sync(0xffffffffu, node, 0);
        if (node >= 32) break;
        int n = nblk + node;
        if (n >= NN) break;

        const __half2* gnode = &sG[node * SROW];
        __half2 G2[16];
#pragma unroll
        for (int k2 = 0; k2 < 16; k2++) G2[k2] = gnode[k2 * 32 + lane];
        float B = __low2float(gnode[640 + lane]);

        int beg = g_rowptr[n], end = beg + g_outdeg[n];
        int pos = beg;
        if (pos + 2 <= end) {
            int4 eA = g_erec[pos], eB = g_erec[pos + 1];
            while (true) {
                int np = pos + 2;
                bool more = np + 2 <= end;
                int4 nA, nB;
                if (more) { nA = g_erec[np]; nB = g_erec[np + 1]; }
                float dd = __int_as_float(edge ? eB.z : eA.z);
                int   rr = edge ? eB.x : eA.x;
                float h0 = fmaxf(fmaf(dd, sW1d[kk2],     sW1rb[rr][kk2]),     0.f);
                float h1 = fmaxf(fmaf(dd, sW1d[kk2 + 1], sW1rb[rr][kk2 + 1]), 0.f);
                u32 myh = pack_h2(h0, h1);

                __half2 z = __float2half2_rn(0.f);
                __half2 a0 = z, a1 = z, b0 = z, b1v = z;
#pragma unroll
                for (int k2 = 0; k2 < 16; k2 += 2) {
                    u32 ha0 = __shfl_sync(0xffffffffu, myh, k2);
                    u32 ha1 = __shfl_sync(0xffffffffu, myh, k2 + 1);
                    u32 hb0 = __shfl_sync(0xffffffffu, myh, 16 + k2);
                    u32 hb1 = __shfl_sync(0xffffffffu, myh, 16 + k2 + 1);
                    a0  = __hfma2(*(__half2*)&ha0, G2[k2],     a0);
                    a1  = __hfma2(*(__half2*)&ha1, G2[k2 + 1], a1);
                    b0  = __hfma2(*(__half2*)&hb0, G2[k2],     b0);
                    b1v = __hfma2(*(__half2*)&hb1, G2[k2 + 1], b1v);
                }
                float2 fA0 = __half22float2(a0), fA1 = __half22float2(a1);
                float2 fB0 = __half22float2(b0), fB1 = __half22float2(b1v);
                float mmA = (fA0.x + fA0.y) + (fA1.x + fA1.y) + B;
                float mmB = (fB0.x + fB0.y) + (fB1.x + fB1.y) + B;
                __half2 xpA = gnode[512 + (eA.x >> 1) * 32 + lane];
                __half2 xpB = gnode[512 + (eB.x >> 1) * 32 + lane];
                float xrA = (eA.x & 1) ? __high2float(xpA) : __low2float(xpA);
                float xrB = (eB.x & 1) ? __high2float(xpB) : __low2float(xpB);
                float dvA = xrA * __int_as_float(eA.y);
                float dvB = xrB * __int_as_float(eB.y);
                msgw[(size_t)eA.w * 32 + lane] = pack_h2(mmA, dvA);
                msgw[(size_t)eB.w * 32 + lane] = pack_h2(mmB, dvB);
                if (!more) break;
                pos = np; eA = nA; eB = nB;
            }
            pos += 2;
        }
        if (pos < end) {   // tail single edge
            int4 eA = g_erec[pos];
            float dd = __int_as_float(eA.z);
            int   rr = eA.x;
            float h0 = fmaxf(fmaf(dd, sW1d[kk2],     sW1rb[rr][kk2]),     0.f);
            float h1 = fmaxf(fmaf(dd, sW1d[kk2 + 1], sW1rb[rr][kk2 + 1]), 0.f);
            u32 myh = pack_h2(h0, h1);
            __half2 z = __float2half2_rn(0.f);
            __half2 a0 = z, a1 = z;
#pragma unroll
            for (int k2 = 0; k2 < 16; k2 += 2) {
                u32 ha0 = __shfl_sync(0xffffffffu, myh, k2);
                u32 ha1 = __shfl_sync(0xffffffffu, myh, k2 + 1);
                a0 = __hfma2(*(__half2*)&ha0, G2[k2],     a0);
                a1 = __hfma2(*(__half2*)&ha1, G2[k2 + 1], a1);
            }
            float2 fA0 = __half22float2(a0), fA1 = __half22float2(a1);
            float mmA = (fA0.x + fA0.y) + (fA1.x + fA1.y) + B;
            __half2 xpA = gnode[512 + (eA.x >> 1) * 32 + lane];
            float xrA = (eA.x & 1) ? __high2float(xpA) : __low2float(xpA);
            float dvA = xrA * __int_as_float(eA.y);
            msgw[(size_t)eA.w * 32 + lane] = pack_h2(mmA, dvA);
        }
    }
}

// ---------------- final gather (last layer) ---------------------------------
__global__ __launch_bounds__(256) void gather_kernel(
    int p, int mb, const float* __restrict__ rbias,
    const float* __restrict__ nbias, float* __restrict__ out_final) {
    int t = threadIdx.x, warp = t >> 5, lane = t & 31;
    int n = blockIdx.x * WPB + warp;
    if (n >= NN) return;
    out_final[(size_t)n * 32 + lane] = gather_node(n, lane, p, mb, rbias, nbias);
}

// ---------------- host launch ------------------------------------------------
extern "C" void kernel_launch(void* const* d_in, const int* in_sizes, int n_in,
                              void* d_out, int out_size) {
    const float* x     = (const float*)d_in[0];
    const int*   eidx  = (const int*)  d_in[1];   // [2,E]: src then dst
    const int*   etype = (const int*)  d_in[2];
    const float* edist = (const float*)d_in[3];
    const float* fcW   = (const float*)d_in[4];
    const float* fcb   = (const float*)d_in[5];
    const float* rW    = (const float*)d_in[6];   // [L,R,32,32]
    const float* rroot = (const float*)d_in[7];   // [L,32,32]
    const float* rbias = (const float*)d_in[8];   // [L,32]
    const float* W1    = (const float*)d_in[9];   // [9,32]
    const float* b1    = (const float*)d_in[10];  // [32]
    const float* W2    = (const float*)d_in[11];  // [32,1024]
    const float* b2    = (const float*)d_in[12];  // [1024]
    const float* nroot = (const float*)d_in[13];  // [L,32,32]
    const float* nbias = (const float*)d_in[14];  // [L,32]
    float* out = (float*)d_out;

    const int* srcp = eidx;
    const int* dstp = eidx + EE;

    int smem = 32 * SROW * 4;  // 98816 bytes
    cudaFuncSetAttribute(fusedmsg_kernel,
                         cudaFuncAttributeMaxDynamicSharedMemorySize, smem);

    init_kernel<<<(NN * NREL + 255) / 256, 256>>>();
    count_kernel<<<(EE + 255) / 256, 256>>>(srcp, dstp, etype);
    assign_kernel<<<(NN * NREL + 255) / 256, 256>>>();
    fill_kernel<<<(EE + 255) / 256, 256>>>(srcp, dstp, etype, edist);
    wcat_kernel<<<(NLAY * NCOL * 32 + 255) / 256, 256>>>(W2, rW, b2, rroot, nroot);
    fc_kernel<<<(NN + WPB - 1) / WPB, WPB * 32>>>(x, fcW, fcb);

    for (int l = 0; l < NLAY; l++) {
        int p = (l == 0) ? 0 : ((l - 1) & 1);
        int lb = (l == 0) ? 0 : (l - 1);
        fusedmsg_kernel<<<(NN + 31) / 32, 512, smem>>>(
            p, l, W1, b1,
            rbias + (size_t)lb * 32, nbias + (size_t)lb * 32,
            l > 0 ? 1 : 0);
    }
    gather_kernel<<<(NN + WPB - 1) / WPB, WPB * 32>>>(
        (NLAY - 1) & 1, (NLAY - 1) & 1,
        rbias + (size_t)(NLAY - 1) * 32,
        nbias + (size_t)(NLAY - 1) * 32, out);
}

// round 15
// speedup vs baseline: 1.2273x; 1.2273x over previous
#include <cuda_runtime.h>
#include <cuda_fp16.h>
#include <cstdint>

#define NN    50000
#define EE    400000
#define NREL  8
#define NLAY  5
#define WPB   8            // warps per block (gather)
#define NCOL  1408         // GEMM N (used cols): 1024 G | 256 Xr | 64 B | 64 roots
#define SROW  708          // smem row stride in half2 (mod 32 == 4: conflict-free)

typedef unsigned int u32;

// ---------------- scratch (static device globals; no allocations) ----------
__device__ __half   g_WcatH[NLAY][NCOL * 32];    // fused fp16 weights, col-major, k-permuted
__device__ __half2  g_roots[NN * 32];            // per-node (rroot,nroot) pairs
__device__ float    g_h[2][NN * 32];
__device__ float    g_invrel[NREL][NN];
__device__ int      g_counter[2];
__device__ int      g_outdeg[NN];
__device__ int      g_indeg[NN];
__device__ int      g_cursor[NN];
__device__ int      g_incur[NN];
__device__ int      g_rowptr[NN];
__device__ int      g_inrow[NN];
__device__ int4     g_erec[EE];                  // {r, wr_bits, dist_bits, dst_slot}
__device__ u32      g_msg2[(size_t)EE * 32];     // per-edge half2(mm, dv), dst order

__device__ __forceinline__ u32 pack_h2(float a, float b) {
    __half2 h = __floats2half2_rn(a, b);
    return *(u32*)&h;
}

// ---------------- init / counts ----------------------------------------------
__global__ void init_kernel() {
    int i = blockIdx.x * blockDim.x + threadIdx.x;
    if (i < 2) g_counter[i] = 0;
    if (i < NN) { g_outdeg[i] = 0; g_indeg[i] = 0; }
    if (i < NN * NREL) ((float*)g_invrel)[i] = 0.f;
}

__global__ void count_kernel(const int* __restrict__ src,
                             const int* __restrict__ dst,
                             const int* __restrict__ etype) {
    int e = blockIdx.x * blockDim.x + threadIdx.x;
    if (e >= EE) return;
    int d = dst[e], r = etype[e];
    atomicAdd(&g_indeg[d], 1);
    atomicAdd(&g_invrel[r][d], 1.f);
    atomicAdd(&g_outdeg[src[e]], 1);
}

// invert rel counts + assign CSR segments (order-free)
__global__ void assign_kernel() {
    int i = blockIdx.x * blockDim.x + threadIdx.x;
    if (i < NN * NREL) {
        float v = ((float*)g_invrel)[i];
        ((float*)g_invrel)[i] = 1.f / fmaxf(v, 1.f);
    }
    if (i < NN) {
        g_rowptr[i] = atomicAdd(&g_counter[0], g_outdeg[i]);
        g_inrow[i]  = atomicAdd(&g_counter[1], g_indeg[i]);
        g_cursor[i] = 0;
        g_incur[i]  = 0;
    }
}

__global__ void fill_kernel(const int* __restrict__ src,
                            const int* __restrict__ dst,
                            const int* __restrict__ etype,
                            const float* __restrict__ edist) {
    int e = blockIdx.x * blockDim.x + threadIdx.x;
    if (e >= EE) return;
    int s = src[e], d = dst[e], r = etype[e];
    int pos = g_rowptr[s] + atomicAdd(&g_cursor[s], 1);
    int pin = g_inrow[d] + atomicAdd(&g_incur[d], 1);
    int4 rec;
    rec.x = r;
    rec.y = __float_as_int(g_invrel[r][d]);
    rec.z = __float_as_int(edist[e]);
    rec.w = pin;
    g_erec[pos] = rec;
}

// ---------------- build fused fp16 weight matrix ------------------------------
// Col-major [j][k-permuted]. Storage slot s in [0,32): kk=s>>4, w=s&15,
// tq=w>>2, slot=w&3 -> original k = kk*16 + (slot<2 ? tq*2+slot : tq*2+8+slot-2).
// This makes each thread's mma B-fragment (b0,b1) one aligned uint2.
__global__ void wcat_kernel(const float* __restrict__ W2,
                            const float* __restrict__ rW,
                            const float* __restrict__ b2,
                            const float* __restrict__ rroot,
                            const float* __restrict__ nroot) {
    int idx = blockIdx.x * blockDim.x + threadIdx.x;
    if (idx >= NLAY * NCOL * 32) return;
    int l = idx / (NCOL * 32);
    int rem = idx % (NCOL * 32);
    int j = rem >> 5, s = rem & 31;
    int kk = s >> 4, w = s & 15, tq = w >> 2, slot = w & 3;
    int i = kk * 16 + ((slot < 2) ? (tq * 2 + slot) : (tq * 2 + 8 + slot - 2));
    int p = j >> 1, par = j & 1;
    float v = 0.f;
    if (p < 512) {
        int k = 2 * (p >> 5) + par, o = p & 31;
        v = W2[k * 1024 + i * 32 + o];
    } else if (p < 640) {
        int r = 2 * ((p - 512) >> 5) + par, o = p & 31;
        v = rW[(((size_t)l * NREL + r) * 32 + i) * 32 + o];
    } else if (p < 672) {
        if (par == 0) v = b2[i * 32 + (p - 640)];
    } else {   // p < 704
        int o = p - 672;
        v = par ? nroot[((size_t)l * 32 + i) * 32 + o]
                : rroot[((size_t)l * 32 + i) * 32 + o];
    }
    g_WcatH[l][rem] = __float2half(v);
}

// ---------------- h0 = relu(x @ fc_W + fc_b) --------------------------------
__global__ __launch_bounds__(WPB * 32) void fc_kernel(
    const float* __restrict__ x, const float* __restrict__ W,
    const float* __restrict__ b) {
    int warp = threadIdx.x >> 5, lane = threadIdx.x & 31;
    int n = blockIdx.x * WPB + warp;
    if (n >= NN) return;
    float xv = x[n * 32 + lane];
    float acc = b[lane];
#pragma unroll
    for (int k = 0; k < 32; k++)
        acc = fmaf(__shfl_sync(0xffffffffu, xv, k), W[k * 32 + lane], acc);
    g_h[0][n * 32 + lane] = fmaxf(acc, 0.f);
}

// ---------------- fused GEMM(mma) + message kernel ---------------------------
// 512 threads, 32 nodes/block.
// Phase 1: passes 0,1 = 512 cols x 16 warps; pass 2 = 384 cols (warps 0-11).
// Phase 2: dynamic node queue; msgs dst-slotted.
__global__ __launch_bounds__(512, 2) void fusedmsg_kernel(
    int p, int l, const float* __restrict__ W1, const float* __restrict__ b1) {
    extern __shared__ __half2 sG[];        // [32][SROW], 90.6 KB
    __shared__ float sW1d[32];             // W1[0][k]
    __shared__ float sW1rb[NREL][32];      // W1[1+r][k] + b1[k]
    __shared__ int   sNext;
    int t = threadIdx.x, warp = t >> 5, lane = t & 31;
    int nblk = blockIdx.x * 32;
    int g = lane >> 2, tq = lane & 3;
    const __half* Wl = g_WcatH[l];
    const float* hp = g_h[p];

    if (t == 0) sNext = 0;
    if (t < 32) sW1d[t] = W1[t];
    else if (t >= 64 && t < 320) {
        int r = (t - 64) >> 5, k = t & 31;
        sW1rb[r][k] = W1[(1 + r) * 32 + k] + b1[k];
    }

    // ---- load A fragments for both m-tiles ----
    u32 afrag[2][2][4];
#pragma unroll
    for (int m = 0; m < 2; m++) {
        int nodeA = nblk + m * 16 + g;
        int nodeB = nodeA + 8;
        bool vA = nodeA < NN, vB = nodeB < NN;
#pragma unroll
        for (int kk = 0; kk < 2; kk++) {
            int kb = kk * 16 + tq * 2;
            float2 f00 = vA ? *(const float2*)&hp[(size_t)nodeA * 32 + kb]
                            : make_float2(0.f, 0.f);
            float2 f01 = vA ? *(const float2*)&hp[(size_t)nodeA * 32 + kb + 8]
                            : make_float2(0.f, 0.f);
            float2 f10 = vB ? *(const float2*)&hp[(size_t)nodeB * 32 + kb]
                            : make_float2(0.f, 0.f);
            float2 f11 = vB ? *(const float2*)&hp[(size_t)nodeB * 32 + kb + 8]
                            : make_float2(0.f, 0.f);
            afrag[m][kk][0] = pack_h2(f00.x, f00.y);
            afrag[m][kk][1] = pack_h2(f10.x, f10.y);
            afrag[m][kk][2] = pack_h2(f01.x, f01.y);
            afrag[m][kk][3] = pack_h2(f11.x, f11.y);
        }
    }

    // ---- phase 1: 3 passes; pass 2 covers only 384 cols (no padding) ----
#pragma unroll
    for (int by2 = 0; by2 < 3; by2++) {
        bool active = (by2 < 2) || (warp < 12);
        if (active) {
            float acc[2][4][4];
#pragma unroll
            for (int m = 0; m < 2; m++)
#pragma unroll
                for (int nt = 0; nt < 4; nt++)
#pragma unroll
                    for (int c = 0; c < 4; c++) acc[m][nt][c] = 0.f;
#pragma unroll
            for (int kk = 0; kk < 2; kk++) {
#pragma unroll
                for (int nt = 0; nt < 4; nt++) {
                    int j = by2 * 512 + warp * 32 + nt * 8 + g;
                    uint2 wv = *(const uint2*)&Wl[j * 32 + kk * 16 + tq * 4];
#pragma unroll
                    for (int m = 0; m < 2; m++) {
                        asm("mma.sync.aligned.m16n8k16.row.col.f32.f16.f16.f32 "
                            "{%0,%1,%2,%3}, {%4,%5,%6,%7}, {%8,%9}, {%0,%1,%2,%3};"
                            : "+f"(acc[m][nt][0]), "+f"(acc[m][nt][1]),
                              "+f"(acc[m][nt][2]), "+f"(acc[m][nt][3])
                            : "r"(afrag[m][kk][0]), "r"(afrag[m][kk][1]),
                              "r"(afrag[m][kk][2]), "r"(afrag[m][kk][3]),
                              "r"(wv.x), "r"(wv.y));
                    }
                }
            }
#pragma unroll
            for (int m = 0; m < 2; m++)
#pragma unroll
                for (int nt = 0; nt < 4; nt++) {
                    int pl = by2 * 256 + warp * 16 + nt * 4 + tq;
                    sG[(m * 16 + g) * SROW + pl] =
                        __floats2half2_rn(acc[m][nt][0], acc[m][nt][1]);
                    sG[(m * 16 + 8 + g) * SROW + pl] =
                        __floats2half2_rn(acc[m][nt][2], acc[m][nt][3]);
                }
        }
    }
    __syncthreads();

    // ---- export roots (pairs 672..703) ----
#pragma unroll
    for (int it = 0; it < 2; it++) {
        int id = it * 512 + t;
        int node = id >> 5, o = id & 31;
        if (nblk + node < NN)
            g_roots[(size_t)(nblk + node) * 32 + o] = sG[node * SROW + 672 + o];
    }

    // ---- phase 2: dynamic node queue ----
    int edge = lane >> 4, kk2 = (lane & 15) * 2;
    while (true) {
        int node = 0;
        if (lane == 0) node = atomicAdd(&sNext, 1);
        node = __shfl_sync(0xffffffffu, node, 0);
        if (node >= 32) break;
        int n = nblk + node;
        if (n >= NN) break;

        const __half2* gnode = &sG[node * SROW];
        __half2 G2[16];
#pragma unroll
        for (int k2 = 0; k2 < 16; k2++) G2[k2] = gnode[k2 * 32 + lane];
        float B = __low2float(gnode[640 + lane]);

        int beg = g_rowptr[n], end = beg + g_outdeg[n];
        int pos = beg;
        if (pos + 2 <= end) {
            int4 eA = g_erec[pos], eB = g_erec[pos + 1];
            while (true) {
                int np = pos + 2;
                bool more = np + 2 <= end;
                int4 nA, nB;
                if (more) { nA = g_erec[np]; nB = g_erec[np + 1]; }
                float dd = __int_as_float(edge ? eB.z : eA.z);
                int   rr = edge ? eB.x : eA.x;
                float h0 = fmaxf(fmaf(dd, sW1d[kk2],     sW1rb[rr][kk2]),     0.f);
                float h1 = fmaxf(fmaf(dd, sW1d[kk2 + 1], sW1rb[rr][kk2 + 1]), 0.f);
                u32 myh = pack_h2(h0, h1);

                __half2 z = __float2half2_rn(0.f);
                __half2 a0 = z, a1 = z, b0 = z, b1v = z;
#pragma unroll
                for (int k2 = 0; k2 < 16; k2 += 2) {
                    u32 ha0 = __shfl_sync(0xffffffffu, myh, k2);
                    u32 ha1 = __shfl_sync(0xffffffffu, myh, k2 + 1);
                    u32 hb0 = __shfl_sync(0xffffffffu, myh, 16 + k2);
                    u32 hb1 = __shfl_sync(0xffffffffu, myh, 16 + k2 + 1);
                    a0  = __hfma2(*(__half2*)&ha0, G2[k2],     a0);
                    a1  = __hfma2(*(__half2*)&ha1, G2[k2 + 1], a1);
                    b0  = __hfma2(*(__half2*)&hb0, G2[k2],     b0);
                    b1v = __hfma2(*(__half2*)&hb1, G2[k2 + 1], b1v);
                }
                float2 fA0 = __half22float2(a0), fA1 = __half22float2(a1);
                float2 fB0 = __half22float2(b0), fB1 = __half22float2(b1v);
                float mmA = (fA0.x + fA0.y) + (fA1.x + fA1.y) + B;
                float mmB = (fB0.x + fB0.y) + (fB1.x + fB1.y) + B;
                __half2 xpA = gnode[512 + (eA.x >> 1) * 32 + lane];
                __half2 xpB = gnode[512 + (eB.x >> 1) * 32 + lane];
                float xrA = (eA.x & 1) ? __high2float(xpA) : __low2float(xpA);
                float xrB = (eB.x & 1) ? __high2float(xpB) : __low2float(xpB);
                float dvA = xrA * __int_as_float(eA.y);
                float dvB = xrB * __int_as_float(eB.y);
                g_msg2[(size_t)eA.w * 32 + lane] = pack_h2(mmA, dvA);
                g_msg2[(size_t)eB.w * 32 + lane] = pack_h2(mmB, dvB);
                if (!more) break;
                pos = np; eA = nA; eB = nB;
            }
            pos += 2;
        }
        if (pos < end) {   // tail single edge
            int4 eA = g_erec[pos];
            float dd = __int_as_float(eA.z);
            int   rr = eA.x;
            float h0 = fmaxf(fmaf(dd, sW1d[kk2],     sW1rb[rr][kk2]),     0.f);
            float h1 = fmaxf(fmaf(dd, sW1d[kk2 + 1], sW1rb[rr][kk2 + 1]), 0.f);
            u32 myh = pack_h2(h0, h1);
            __half2 z = __float2half2_rn(0.f);
            __half2 a0 = z, a1 = z;
#pragma unroll
            for (int k2 = 0; k2 < 16; k2 += 2) {
                u32 ha0 = __shfl_sync(0xffffffffu, myh, k2);
                u32 ha1 = __shfl_sync(0xffffffffu, myh, k2 + 1);
                a0 = __hfma2(*(__half2*)&ha0, G2[k2],     a0);
                a1 = __hfma2(*(__half2*)&ha1, G2[k2 + 1], a1);
            }
            float2 fA0 = __half22float2(a0), fA1 = __half22float2(a1);
            float mmA = (fA0.x + fA0.y) + (fA1.x + fA1.y) + B;
            __half2 xpA = gnode[512 + (eA.x >> 1) * 32 + lane];
            float xrA = (eA.x & 1) ? __high2float(xpA) : __low2float(xpA);
            float dvA = xrA * __int_as_float(eA.y);
            g_msg2[(size_t)eA.w * 32 + lane] = pack_h2(mmA, dvA);
        }
    }
}

// ---------------- per-layer gather + combine (warp per destination) ---------
__global__ __launch_bounds__(256) void gather_kernel(
    int p, const float* __restrict__ rbias, const float* __restrict__ nbias,
    float* __restrict__ out_final) {
    int t = threadIdx.x, warp = t >> 5, lane = t & 31;
    int n = blockIdx.x * WPB + warp;
    if (n >= NN) return;

    int beg = g_inrow[n], cnt = g_indeg[n];
    const u32* base = &g_msg2[(size_t)beg * 32 + lane];
    float mms = 0.f, dvs = 0.f;
    int j = 0;
    for (; j + 8 <= cnt; j += 8) {
        u32 v0 = base[(j + 0) * 32];
        u32 v1 = base[(j + 1) * 32];
        u32 v2 = base[(j + 2) * 32];
        u32 v3 = base[(j + 3) * 32];
        u32 v4 = base[(j + 4) * 32];
        u32 v5 = base[(j + 5) * 32];
        u32 v6 = base[(j + 6) * 32];
        u32 v7 = base[(j + 7) * 32];
        float2 f0 = __half22float2(*(__half2*)&v0);
        float2 f1 = __half22float2(*(__half2*)&v1);
        float2 f2 = __half22float2(*(__half2*)&v2);
        float2 f3 = __half22float2(*(__half2*)&v3);
        float2 f4 = __half22float2(*(__half2*)&v4);
        float2 f5 = __half22float2(*(__half2*)&v5);
        float2 f6 = __half22float2(*(__half2*)&v6);
        float2 f7 = __half22float2(*(__half2*)&v7);
        mms += ((f0.x + f1.x) + (f2.x + f3.x)) + ((f4.x + f5.x) + (f6.x + f7.x));
        dvs += ((f0.y + f1.y) + (f2.y + f3.y)) + ((f4.y + f5.y) + (f6.y + f7.y));
    }
    for (; j < cnt; j++) {
        u32 v = base[j * 32];
        float2 f = __half22float2(*(__half2*)&v);
        mms += f.x;
        dvs += f.y;
    }
    float invd = 1.f / fmaxf((float)cnt, 1.f);

    size_t idx = (size_t)n * 32 + lane;
    float2 roots = __half22float2(g_roots[idx]);
    float hv = g_h[p][idx];
    float v = hv + fmaxf(roots.x + rbias[lane] + dvs, 0.f)
                 + fmaxf(roots.y + nbias[lane] + mms * invd, 0.f);
    if (out_final) out_final[idx] = v;
    else           g_h[p ^ 1][idx] = v;
}

// ---------------- host launch ------------------------------------------------
extern "C" void kernel_launch(void* const* d_in, const int* in_sizes, int n_in,
                              void* d_out, int out_size) {
    const float* x     = (const float*)d_in[0];
    const int*   eidx  = (const int*)  d_in[1];   // [2,E]: src then dst
    const int*   etype = (const int*)  d_in[2];
    const float* edist = (const float*)d_in[3];
    const float* fcW   = (const float*)d_in[4];
    const float* fcb   = (const float*)d_in[5];
    const float* rW    = (const float*)d_in[6];   // [L,R,32,32]
    const float* rroot = (const float*)d_in[7];   // [L,32,32]
    const float* rbias = (const float*)d_in[8];   // [L,32]
    const float* W1    = (const float*)d_in[9];   // [9,32]
    const float* b1    = (const float*)d_in[10];  // [32]
    const float* W2    = (const float*)d_in[11];  // [32,1024]
    const float* b2    = (const float*)d_in[12];  // [1024]
    const float* nroot = (const float*)d_in[13];  // [L,32,32]
    const float* nbias = (const float*)d_in[14];  // [L,32]
    float* out = (float*)d_out;

    const int* srcp = eidx;
    const int* dstp = eidx + EE;

    int smem = 32 * SROW * 4;  // 90624 bytes
    cudaFuncSetAttribute(fusedmsg_kernel,
                         cudaFuncAttributeMaxDynamicSharedMemorySize, smem);

    init_kernel<<<(NN * NREL + 255) / 256, 256>>>();
    count_kernel<<<(EE + 255) / 256, 256>>>(srcp, dstp, etype);
    assign_kernel<<<(NN * NREL + 255) / 256, 256>>>();
    fill_kernel<<<(EE + 255) / 256, 256>>>(srcp, dstp, etype, edist);
    wcat_kernel<<<(NLAY * NCOL * 32 + 255) / 256, 256>>>(W2, rW, b2, rroot, nroot);
    fc_kernel<<<(NN + WPB - 1) / WPB, WPB * 32>>>(x, fcW, fcb);

    for (int l = 0; l < NLAY; l++) {
        int p = l & 1;
        fusedmsg_kernel<<<(NN + 31) / 32, 512, smem>>>(p, l, W1, b1);
        gather_kernel<<<(NN + WPB - 1) / WPB, WPB * 32>>>(
            p, rbias + (size_t)l * 32, nbias + (size_t)l * 32,
            (l == NLAY - 1) ? out : nullptr);
    }
}